// round 5
// baseline (speedup 1.0000x reference)
#include <cuda_runtime.h>
#include <math.h>

#define Bb   32
#define Ll   512
#define Hh   256
#define EMB  300
#define NH   8
#define HD   32
#define L1   513
#define NITER 6

// ------------------------- scratch (static, no allocs) -------------------------
__device__ float g_x0 [Bb*Ll*Hh];   // nodes
__device__ float g_ln [Bb*Ll*Hh];
__device__ float g_q  [Bb*Ll*Hh];
__device__ float g_k  [Bb*Ll*Hh];
__device__ float g_att[Bb*Ll*Hh];
__device__ float g_y  [Bb*L1*Hh];
__device__ float g_k2 [Bb*L1*Hh];
__device__ float g_v2 [Bb*L1*Hh];
__device__ float g_relay[Bb*Hh];
__device__ float g_ak [Bb*Hh];
__device__ float g_av [Bb*Hh];
__device__ float g_q2 [Bb*Hh];
__device__ float g_att2[Bb*Hh];

// ------------------------- embedding: x0 = emb[data]@W + b + pos ---------------
__global__ __launch_bounds__(256) void embed_k(
    const int* __restrict__ data, const float* __restrict__ emb,
    const float* __restrict__ W, const float* __restrict__ bias,
    const float* __restrict__ pos, float* __restrict__ x0)
{
    __shared__ float As[32][EMB];     // 32 gathered embedding rows (38.4 KB)
    __shared__ int   toks[32];
    const int r0 = blockIdx.x * 32;
    const int t  = threadIdx.x;
    if (t < 32) toks[t] = data[r0 + t];
    __syncthreads();
    for (int i = t; i < 32 * EMB; i += 256) {
        int r = i / EMB, e = i - r * EMB;
        As[r][e] = emb[toks[r] * EMB + e];
    }
    __syncthreads();
    float acc[32];
    #pragma unroll
    for (int r = 0; r < 32; r++) acc[r] = 0.f;
    for (int e = 0; e < EMB; e++) {
        float w = W[e * Hh + t];
        #pragma unroll
        for (int r = 0; r < 32; r++) acc[r] += As[r][e] * w;
    }
    const float bs = bias[t];
    #pragma unroll
    for (int r = 0; r < 32; r++) {
        int row = r0 + r;
        int l   = row & (Ll - 1);
        x0[row * Hh + t] = acc[r] + bs + pos[l * Hh + t];
    }
}

// ------------------------- relay init: mean over L -----------------------------
__global__ __launch_bounds__(256) void relay_init_k(
    const float* __restrict__ x0, float* __restrict__ relay)
{
    const int b = blockIdx.x, t = threadIdx.x;
    float s = 0.f;
    for (int l = 0; l < Ll; l++) s += x0[(b * Ll + l) * Hh + t];
    relay[b * Hh + t] = s * (1.f / Ll);
}

// ------------------------- layernorm over H=256 --------------------------------
__global__ __launch_bounds__(256) void ln_k(
    const float* __restrict__ x, const float* __restrict__ g,
    const float* __restrict__ b, float* __restrict__ out)
{
    const int row = blockIdx.x, t = threadIdx.x;
    float v = x[row * Hh + t];
    float s = v;
    #pragma unroll
    for (int o = 16; o; o >>= 1) s += __shfl_xor_sync(0xffffffffu, s, o);
    __shared__ float red1[8], red2[8];
    if ((t & 31) == 0) red1[t >> 5] = s;
    __syncthreads();
    float tot = 0.f;
    #pragma unroll
    for (int w = 0; w < 8; w++) tot += red1[w];
    const float mu = tot * (1.f / Hh);
    float dv = v - mu;
    float s2 = dv * dv;
    #pragma unroll
    for (int o = 16; o; o >>= 1) s2 += __shfl_xor_sync(0xffffffffu, s2, o);
    if ((t & 31) == 0) red2[t >> 5] = s2;
    __syncthreads();
    float vtot = 0.f;
    #pragma unroll
    for (int w = 0; w < 8; w++) vtot += red2[w];
    const float var = vtot * (1.f / Hh);
    out[row * Hh + t] = g[t] * dv * rsqrtf(var + 1e-5f) + b[t];
}

// ------------------------- GEMM: C[M,256] = A[M,256] @ W[256,256] + bias -------
// MODE 0: store     MODE 1: C += leaky_relu(.)   (residual into C)
#define BM 128
#define BN 64
#define BK 16
template <int MODE>
__global__ __launch_bounds__(256) void gemm256(
    const float* __restrict__ A, const float* __restrict__ W,
    const float* __restrict__ bias, float* __restrict__ C, int M)
{
    __shared__ float As[BK][BM];
    __shared__ float Bs[BK][BN];
    const int t  = threadIdx.x;
    const int m0 = blockIdx.x * BM;
    const int n0 = blockIdx.y * BN;
    const int tx = t & 15;          // 0..15 -> col group (4 cols)
    const int ty = t >> 4;          // 0..15 -> row group (8 rows)
    const int ar = t >> 1;          // 0..127
    const int ac = (t & 1) * 8;     // 0 or 8
    const int wr = t >> 4;          // 0..15
    const int wc = (t & 15) * 4;    // 0..60

    float acc[8][4];
    #pragma unroll
    for (int i = 0; i < 8; i++)
        #pragma unroll
        for (int j = 0; j < 4; j++) acc[i][j] = 0.f;

    for (int kt = 0; kt < 256; kt += BK) {
        const int row = m0 + ar;
        if (row < M) {
            float4 a0 = *reinterpret_cast<const float4*>(A + row * 256 + kt + ac);
            float4 a1 = *reinterpret_cast<const float4*>(A + row * 256 + kt + ac + 4);
            As[ac + 0][ar] = a0.x; As[ac + 1][ar] = a0.y;
            As[ac + 2][ar] = a0.z; As[ac + 3][ar] = a0.w;
            As[ac + 4][ar] = a1.x; As[ac + 5][ar] = a1.y;
            As[ac + 6][ar] = a1.z; As[ac + 7][ar] = a1.w;
        } else {
            #pragma unroll
            for (int i = 0; i < 8; i++) As[ac + i][ar] = 0.f;
        }
        *reinterpret_cast<float4*>(&Bs[wr][wc]) =
            *reinterpret_cast<const float4*>(W + (kt + wr) * 256 + n0 + wc);
        __syncthreads();
        #pragma unroll
        for (int k = 0; k < BK; k++) {
            const float4 bv = *reinterpret_cast<const float4*>(&Bs[k][tx * 4]);
            const float4 a0 = *reinterpret_cast<const float4*>(&As[k][ty * 8]);
            const float4 a1 = *reinterpret_cast<const float4*>(&As[k][ty * 8 + 4]);
            const float av8[8] = {a0.x, a0.y, a0.z, a0.w, a1.x, a1.y, a1.z, a1.w};
            const float bv4[4] = {bv.x, bv.y, bv.z, bv.w};
            #pragma unroll
            for (int i = 0; i < 8; i++)
                #pragma unroll
                for (int j = 0; j < 4; j++)
                    acc[i][j] += av8[i] * bv4[j];
        }
        __syncthreads();
    }

    float bb[4];
    #pragma unroll
    for (int j = 0; j < 4; j++) bb[j] = bias[n0 + tx * 4 + j];
    #pragma unroll
    for (int i = 0; i < 8; i++) {
        const int row = m0 + ty * 8 + i;
        if (row < M) {
            #pragma unroll
            for (int j = 0; j < 4; j++) {
                float v = acc[i][j] + bb[j];
                const int idx = row * 256 + n0 + tx * 4 + j;
                if (MODE == 1) {
                    v = v > 0.f ? v : 0.01f * v;
                    C[idx] = C[idx] + v;
                } else {
                    C[idx] = v;
                }
            }
        }
    }
}

// ------------------------- small GEMM: [32,256]@[256,256] ----------------------
__global__ __launch_bounds__(256) void small_gemm(
    const float* __restrict__ x, const float* __restrict__ W,
    const float* __restrict__ bias, float* __restrict__ out, int do_leaky)
{
    __shared__ float xr[Hh];
    const int b = blockIdx.x, t = threadIdx.x;
    xr[t] = x[b * Hh + t];
    __syncthreads();
    float acc = bias[t];
    #pragma unroll 8
    for (int k = 0; k < Hh; k++) acc += xr[k] * W[k * Hh + t];
    if (do_leaky) acc = acc > 0.f ? acc : 0.01f * acc;
    out[b * Hh + t] = acc;
}

// ------------------------- msa1 attention (window-3 + relay) -------------------
__global__ __launch_bounds__(256) void attn1_k(
    const float* __restrict__ q, const float* __restrict__ k,
    const float* __restrict__ ak, const float* __restrict__ av,
    float* __restrict__ att)
{
    const int row = blockIdx.x;          // b*512 + l
    const int b = row >> 9, l = row & (Ll - 1);
    const int c = threadIdx.x;           // head*32 + d
    const float qv = q[row * Hh + c];
    const float k0 = ak[b * Hh + c];
    const float v0 = av[b * Hh + c];
    const float km = (l > 0)      ? k[(row - 1) * Hh + c] : 0.f;
    const float kc = k[row * Hh + c];
    const float kp = (l < Ll - 1) ? k[(row + 1) * Hh + c] : 0.f;
    float s0 = qv * k0, s1 = qv * km, s2 = qv * kc, s3 = qv * kp;
    #pragma unroll
    for (int o = 16; o; o >>= 1) {
        s0 += __shfl_xor_sync(0xffffffffu, s0, o);
        s1 += __shfl_xor_sync(0xffffffffu, s1, o);
        s2 += __shfl_xor_sync(0xffffffffu, s2, o);
        s3 += __shfl_xor_sync(0xffffffffu, s3, o);
    }
    const float sc = 0.17677669529663687f;   // 1/sqrt(32)
    s0 *= sc; s1 *= sc; s2 *= sc; s3 *= sc;
    float mx = fmaxf(fmaxf(s0, s1), fmaxf(s2, s3));
    float e0 = expf(s0 - mx), e1 = expf(s1 - mx), e2 = expf(s2 - mx), e3 = expf(s3 - mx);
    const float inv = 1.f / (e0 + e1 + e2 + e3);
    // NOTE: window values come from K (faithful to reference bug)
    att[row * Hh + c] = (e0 * v0 + e1 * km + e2 * kc + e3 * kp) * inv;
}

// ------------------------- build y = [relay; nodes] ----------------------------
__global__ __launch_bounds__(256) void build_y_k(
    const float* __restrict__ relay, const float* __restrict__ nodes,
    float* __restrict__ y)
{
    const int idx = blockIdx.x * 256 + threadIdx.x;
    if (idx >= Bb * L1 * Hh) return;
    const int h  = idx & (Hh - 1);
    const int bl = idx >> 8;
    const int b  = bl / L1;
    const int l1 = bl - b * L1;
    y[idx] = (l1 == 0) ? relay[b * Hh + h] : nodes[(b * Ll + l1 - 1) * Hh + h];
}

// ------------------------- msa2 attention (relay over 513 keys) ----------------
__global__ __launch_bounds__(256) void attn2_k(
    const float* __restrict__ q2, const float* __restrict__ k2,
    const float* __restrict__ v2, float* __restrict__ att2)
{
    const int b = blockIdx.x, n = blockIdx.y;
    const int w = threadIdx.x >> 5, d = threadIdx.x & 31;
    const int t = threadIdx.x;
    __shared__ float sc[L1];
    __shared__ float red[8];
    __shared__ float part[8][32];
    const float qv = q2[b * Hh + n * HD + d];
    for (int j = w; j < L1; j += 8) {
        float p = qv * k2[(b * L1 + j) * Hh + n * HD + d];
        #pragma unroll
        for (int o = 16; o; o >>= 1) p += __shfl_xor_sync(0xffffffffu, p, o);
        if (d == 0) sc[j] = p * 0.17677669529663687f;
    }
    __syncthreads();
    // block max
    float mx = -3.4e38f;
    for (int j = t; j < L1; j += 256) mx = fmaxf(mx, sc[j]);
    #pragma unroll
    for (int o = 16; o; o >>= 1) mx = fmaxf(mx, __shfl_xor_sync(0xffffffffu, mx, o));
    if (d == 0) red[w] = mx;
    __syncthreads();
    float gmx = red[0];
    #pragma unroll
    for (int r = 1; r < 8; r++) gmx = fmaxf(gmx, red[r]);
    __syncthreads();
    // exp + sum
    float ls = 0.f;
    for (int j = t; j < L1; j += 256) { float e = expf(sc[j] - gmx); sc[j] = e; ls += e; }
    #pragma unroll
    for (int o = 16; o; o >>= 1) ls += __shfl_xor_sync(0xffffffffu, ls, o);
    if (d == 0) red[w] = ls;
    __syncthreads();
    float tot = 0.f;
    #pragma unroll
    for (int r = 0; r < 8; r++) tot += red[r];
    const float inv = 1.f / tot;
    // weighted sum over V
    float acc = 0.f;
    for (int j = w; j < L1; j += 8) acc += sc[j] * v2[(b * L1 + j) * Hh + n * HD + d];
    part[w][d] = acc;
    __syncthreads();
    if (w == 0) {
        float s = 0.f;
        #pragma unroll
        for (int r = 0; r < 8; r++) s += part[r][d];
        att2[b * Hh + n * HD + d] = s * inv;
    }
}

// ------------------------- mask: nodes[data==1] = 0 ----------------------------
__global__ __launch_bounds__(256) void mask_k(
    const int* __restrict__ data, float* __restrict__ nodes)
{
    const int idx = blockIdx.x * 256 + threadIdx.x;   // 0..16383
    if (idx >= Bb * Ll) return;
    if (data[idx] == 1) {
        float4 z = make_float4(0.f, 0.f, 0.f, 0.f);
        float4* p = reinterpret_cast<float4*>(nodes + idx * Hh);
        #pragma unroll
        for (int i = 0; i < Hh / 4; i++) p[i] = z;
    }
}

// ------------------------- final: rep = 0.5*max_l nodes + 0.5*relay ------------
__global__ __launch_bounds__(256) void final_k(
    const float* __restrict__ nodes, const float* __restrict__ relay,
    float* __restrict__ out)
{
    const int b = blockIdx.x, t = threadIdx.x;
    float m = -3.4e38f;
    for (int l = 0; l < Ll; l++) m = fmaxf(m, nodes[(b * Ll + l) * Hh + t]);
    out[b * Hh + t] = 0.5f * m + 0.5f * relay[b * Hh + t];
}

// ------------------------- launch ----------------------------------------------
extern "C" void kernel_launch(void* const* d_in, const int* in_sizes, int n_in,
                              void* d_out, int out_size)
{
    (void)in_sizes; (void)n_in; (void)out_size;
    const int*   data     = (const int*)  d_in[0];
    const float* emb      = (const float*)d_in[1];
    const float* emb_fc_W = (const float*)d_in[2];
    const float* emb_fc_b = (const float*)d_in[3];
    const float* pos_emb  = (const float*)d_in[4];
    const float* ln_g     = (const float*)d_in[5];
    const float* ln_b     = (const float*)d_in[6];
    const float* r_WQ = (const float*)d_in[7];
    const float* r_bQ = (const float*)d_in[8];
    const float* r_WK = (const float*)d_in[9];
    const float* r_bK = (const float*)d_in[10];
    const float* r_WV = (const float*)d_in[11];
    const float* r_bV = (const float*)d_in[12];
    const float* r_WO = (const float*)d_in[13];
    const float* r_bO = (const float*)d_in[14];
    const float* s_WQ = (const float*)d_in[15];
    const float* s_bQ = (const float*)d_in[16];
    const float* s_WK = (const float*)d_in[17];
    const float* s_bK = (const float*)d_in[18];
    const float* s_WV = (const float*)d_in[19];
    const float* s_bV = (const float*)d_in[20];
    const float* s_WO = (const float*)d_in[21];
    const float* s_bO = (const float*)d_in[22];

    float *x0, *ln, *q, *k, *att, *y, *k2, *v2, *relay, *ak, *av, *q2, *att2;
    cudaGetSymbolAddress((void**)&x0,   g_x0);
    cudaGetSymbolAddress((void**)&ln,   g_ln);
    cudaGetSymbolAddress((void**)&q,    g_q);
    cudaGetSymbolAddress((void**)&k,    g_k);
    cudaGetSymbolAddress((void**)&att,  g_att);
    cudaGetSymbolAddress((void**)&y,    g_y);
    cudaGetSymbolAddress((void**)&k2,   g_k2);
    cudaGetSymbolAddress((void**)&v2,   g_v2);
    cudaGetSymbolAddress((void**)&relay,g_relay);
    cudaGetSymbolAddress((void**)&ak,   g_ak);
    cudaGetSymbolAddress((void**)&av,   g_av);
    cudaGetSymbolAddress((void**)&q2,   g_q2);
    cudaGetSymbolAddress((void**)&att2, g_att2);

    const int M1 = Bb * Ll;      // 16384
    const int M2 = Bb * L1;      // 16416
    const dim3 gg1((M1 + BM - 1) / BM, 256 / BN);
    const dim3 gg2((M2 + BM - 1) / BM, 256 / BN);

    embed_k<<<Bb * Ll / 32, 256>>>(data, emb, emb_fc_W, emb_fc_b, pos_emb, x0);
    relay_init_k<<<Bb, 256>>>(x0, relay);

    for (int i = 0; i < NITER; i++) {
        const int wo = i * Hh * Hh;
        const int bo = i * Hh;
        ln_k<<<M1, 256>>>(x0, ln_g + bo, ln_b + bo, ln);
        gemm256<0><<<gg1, 256>>>(ln, r_WQ + wo, r_bQ + bo, q, M1);
        gemm256<0><<<gg1, 256>>>(ln, r_WK + wo, r_bK + bo, k, M1);
        small_gemm<<<Bb, 256>>>(relay, r_WK + wo, r_bK + bo, ak, 0);
        small_gemm<<<Bb, 256>>>(relay, r_WV + wo, r_bV + bo, av, 0);
        small_gemm<<<Bb, 256>>>(relay, s_WQ + wo, s_bQ + bo, q2, 0);
        attn1_k<<<M1, 256>>>(q, k, ak, av, att);
        gemm256<1><<<gg1, 256>>>(att, r_WO + wo, r_bO + bo, x0, M1);   // nodes += leaky(att@WO+b)
        build_y_k<<<(Bb * L1 * Hh + 255) / 256, 256>>>(relay, x0, y);
        gemm256<0><<<gg2, 256>>>(y, s_WK + wo, s_bK + bo, k2, M2);
        gemm256<0><<<gg2, 256>>>(y, s_WV + wo, s_bV + bo, v2, M2);
        attn2_k<<<dim3(Bb, NH), 256>>>(q2, k2, v2, att2);
        small_gemm<<<Bb, 256>>>(att2, s_WO + wo, s_bO + bo, relay, 1); // relay = leaky(...)
        mask_k<<<(Bb * Ll + 255) / 256, 256>>>(data, x0);
    }
    final_k<<<Bb, 256>>>(x0, relay, (float*)d_out);
}